// round 4
// baseline (speedup 1.0000x reference)
#include <cuda_runtime.h>

#define D   128   // LATDIM
#define AA  64    // ANCHOR_SET_NUM
#define TN  96    // n per main tile -> 105 main blocks
#define NVB 8     // V-gemm blocks (8 anchors each)

// __device__ scratch (allocation-free rule)
__device__ float g_V[AA * D];
__device__ float g_C[1024 * D];     // T = 625 for N=10000
__device__ float g_S[1024 * D];
__device__ unsigned g_bar1 = 0u, g_bar2 = 0u;

// ---------------------------------------------------------------------------
// packed f32x2 helpers (FFMA2 — PTX-only on sm_103a)
// ---------------------------------------------------------------------------
__device__ __forceinline__ unsigned long long pk2(float x, float y) {
    unsigned long long r;
    asm("mov.b64 %0, {%1, %2};" : "=l"(r) : "f"(x), "f"(y));
    return r;
}
__device__ __forceinline__ void unpk2(unsigned long long v, float& x, float& y) {
    asm("mov.b64 {%0, %1}, %2;" : "=f"(x), "=f"(y) : "l"(v));
}
__device__ __forceinline__ void ffma2(unsigned long long& a,
                                      unsigned long long b, unsigned long long c) {
    asm("fma.rn.f32x2 %0, %1, %2, %0;" : "+l"(a) : "l"(b), "l"(c));
}
__device__ __forceinline__ void fadd2(unsigned long long& a, unsigned long long b) {
    asm("add.rn.f32x2 %0, %0, %1;" : "+l"(a) : "l"(b));
}
__device__ __forceinline__ ulonglong2 ldcg2(const float* p) {
    ulonglong2 r;
    asm("ld.global.cg.v2.u64 {%0, %1}, [%2];" : "=l"(r.x), "=l"(r.y) : "l"(p));
    return r;
}

// ---------------------------------------------------------------------------
// grid barrier: monotonic counter, wrap-safe, valid across graph replays
// (each execution adds exactly gridDim arrivals; cohort end = target).
// ---------------------------------------------------------------------------
__device__ __forceinline__ unsigned bar_arrive(unsigned* c, unsigned nb) {
    __threadfence();
    unsigned old = atomicAdd(c, 1u);
    return old - old % nb + nb;
}
__device__ __forceinline__ void bar_wait(unsigned* c, unsigned tgt) {
    volatile unsigned* vc = (volatile unsigned*)c;
    while ((int)(*vc - tgt) < 0) __nanosleep(64);
    __threadfence();
}

// ---------------------------------------------------------------------------
// shared memory union: gemm staging vs main dists tile (24 KB)
// ---------------------------------------------------------------------------
struct SmemGemm {
    float XT[D][10];     // [k][t-row], pad 10 (rows 8B-aligned for u64 LDS)
    float Wc[32][129];   // [k-chunk][o], pad 129 -> conflict-free staging
};
union Smem {
    SmemGemm g;
    float sd[AA][TN];
};

// ---------------------------------------------------------------------------
// one 8-row tile of X[R,128] @ W-half^T -> dst rows, scaled 1/A (+bias for C)
// 512 threads: o = tid&127, gq = tid>>7 handles t-rows {2gq, 2gq+1} (1 ull acc)
// ---------------------------------------------------------------------------
template<bool IS_C>
__device__ __forceinline__ void tile_gemm(Smem* s,
                                          const float* __restrict__ W,
                                          const float* __restrict__ b,
                                          const float* __restrict__ embeds,
                                          const int*   __restrict__ anchor,
                                          int base, int R, int T, int step,
                                          float* __restrict__ dst) {
    const int tid  = threadIdx.x;
    const int woff = IS_C ? D : 0;

    // build XT[k][r]
    {
        const int k  = tid & 127;
        const int rg = tid >> 7;
        #pragma unroll
        for (int r = rg; r < 8; r += 4) {
            float val = 0.f;
            if (r < R) {
                if (IS_C) {
                    #pragma unroll 4
                    for (int c = 0; c < step; c++) {
                        int t = base + r + c; if (t >= T) t -= T;
                        val += __ldcg(&g_S[(size_t)t * D + k]);
                    }
                } else {
                    const int row = __ldg(&anchor[base + r]);
                    val = __ldg(&embeds[(size_t)row * D + k]);
                }
            }
            s->g.XT[k][r] = val;
        }
    }
    __syncthreads();

    const int o  = tid & 127;
    const int gq = tid >> 7;
    unsigned long long acc = 0ull;

    #pragma unroll
    for (int kc = 0; kc < 4; kc++) {
        // stage Wc[k][o] for k in [32kc, 32kc+32), transposed, coalesced
        #pragma unroll
        for (int it = 0; it < 2; it++) {
            const int idx  = tid + it * 512;
            const int orow = idx >> 3;
            const int kq   = (idx & 7) * 4;
            const float4 wv = *(const float4*)&W[(size_t)orow * (2 * D) + woff + kc * 32 + kq];
            s->g.Wc[kq + 0][orow] = wv.x;
            s->g.Wc[kq + 1][orow] = wv.y;
            s->g.Wc[kq + 2][orow] = wv.z;
            s->g.Wc[kq + 3][orow] = wv.w;
        }
        __syncthreads();
        #pragma unroll 8
        for (int kk = 0; kk < 32; kk++) {
            const float wv = s->g.Wc[kk][o];
            const unsigned long long x =
                *(const unsigned long long*)&s->g.XT[kc * 32 + kk][2 * gq];  // broadcast
            ffma2(acc, x, pk2(wv, wv));
        }
        __syncthreads();
    }

    float r0, r1;
    unpk2(acc, r0, r1);
    const float sc   = 1.0f / AA;
    const float bias = IS_C ? __ldg(&b[o]) : 0.f;
    const int   row0 = 2 * gq;
    if (row0 < R)     dst[(size_t)(base + row0)     * D + o] = r0 * sc + bias;
    if (row0 + 1 < R) dst[(size_t)(base + row0 + 1) * D + o] = r1 * sc + bias;
}

// ---------------------------------------------------------------------------
// the single fused kernel
// ---------------------------------------------------------------------------
__global__ __launch_bounds__(512)
void fused(const float* __restrict__ embeds,
           const float* __restrict__ dists,
           const float* __restrict__ W,
           const float* __restrict__ b,
           const int*   __restrict__ anchor,
           float* __restrict__ out,
           int N, int T, int step, int g, int nMain, int nCtiles) {
    __shared__ __align__(16) Smem s;

    const int x   = blockIdx.x;
    const int NB  = gridDim.x;
    const int tid = threadIdx.x;
    const int w   = tid >> 5;
    const int l   = tid & 31;

    const bool isMain = (x < nMain);
    const bool isV    = (x >= nMain) && (x < nMain + NVB);
    const bool isC    = (x >= nMain + NVB);
    const int  nCB    = NB - nMain - NVB;

    // ---- phase 0: main blocks stage their dists tile early (overlaps S) ----
    const int n0 = x * TN;
    if (isMain) {
        #pragma unroll
        for (int i = tid; i < AA * TN / 4; i += 512) {
            const int a  = i / (TN / 4);
            const int j4 = (i % (TN / 4)) * 4;
            const int n  = n0 + j4;
            const float* src = dists + (size_t)a * N + n;
            float4 v;
            if (n + 3 < N) v = *(const float4*)src;
            else {
                v.x = (n + 0 < N) ? src[0] : 0.f;
                v.y = (n + 1 < N) ? src[1] : 0.f;
                v.z = (n + 2 < N) ? src[2] : 0.f;
                v.w = (n + 3 < N) ? src[3] : 0.f;
            }
            ((float4*)s.sd)[i] = v;
        }
    }

    // ---- phase 1: S chunk sums, warp-distributed over non-V blocks --------
    if (!isV) {
        const int sb  = (x < nMain) ? x : x - NVB;     // 0..(NB-NVB-1) contiguous
        const int NSB = NB - NVB;
        for (int t = sb * 16 + w; t < T; t += NSB * 16) {
            const float* p = embeds + (size_t)t * g * D + 4 * l;
            float4 acc = {0.f, 0.f, 0.f, 0.f};
            #pragma unroll 16
            for (int r = 0; r < 16; r++) {             // g == 16 for N=10000
                const float4 v = __ldg((const float4*)(p + (size_t)r * D));
                acc.x += v.x; acc.y += v.y; acc.z += v.z; acc.w += v.w;
            }
            *(float4*)&g_S[(size_t)t * D + 4 * l] = acc;
        }
    }

    // ---- phase 1b: V gemm (independent of S, pre-barrier) ------------------
    if (isV) {
        __syncthreads();
        tile_gemm<false>(&s, W, b, embeds, anchor,
                         (x - nMain) * 8, 8, T, step, g_V);
    }

    // ---- barrier 1 arrive (+ bar2 arrive for non-C blocks) -----------------
    __syncthreads();
    unsigned tgt1 = 0, tgt2 = 0;
    if (tid == 0) {
        tgt1 = bar_arrive(&g_bar1, NB);
        if (!isC) tgt2 = bar_arrive(&g_bar2, NB);
    }
    if (isV) return;   // arrived at both barriers; done

    if (tid == 0) bar_wait(&g_bar1, tgt1);
    __syncthreads();

    // ---- phase 2: C gemm on dedicated blocks (overlaps main accumulate) ----
    if (isC) {
        for (int tile = x - nMain - NVB; tile < nCtiles; tile += nCB) {
            const int base = tile * 8;
            tile_gemm<true>(&s, W, b, embeds, anchor,
                            base, min(8, T - base), T, step, g_C);
            __syncthreads();
        }
        if (tid == 0) bar_arrive(&g_bar2, NB);
        return;
    }

    // ---- phase 2: main accumulate (V via L2, dists tile in smem) -----------
    const int ob = w * 8;          // warp -> o-chunk of 8
    unsigned long long acc[3][4];
    #pragma unroll
    for (int i = 0; i < 3; i++)
        #pragma unroll
        for (int j = 0; j < 4; j++) acc[i][j] = 0ull;

    #pragma unroll 8
    for (int a = 0; a < AA; a++) {
        const ulonglong2 v01 = ldcg2(&g_V[a * D + ob]);       // uniform per warp
        const ulonglong2 v23 = ldcg2(&g_V[a * D + ob + 4]);
        const float d0 = s.sd[a][l];
        const float d1 = s.sd[a][l + 32];
        const float d2 = s.sd[a][l + 64];
        const unsigned long long dd0 = pk2(d0, d0);
        const unsigned long long dd1 = pk2(d1, d1);
        const unsigned long long dd2 = pk2(d2, d2);

        ffma2(acc[0][0], dd0, v01.x); ffma2(acc[0][1], dd0, v01.y);
        ffma2(acc[0][2], dd0, v23.x); ffma2(acc[0][3], dd0, v23.y);
        ffma2(acc[1][0], dd1, v01.x); ffma2(acc[1][1], dd1, v01.y);
        ffma2(acc[1][2], dd1, v23.x); ffma2(acc[1][3], dd1, v23.y);
        ffma2(acc[2][0], dd2, v01.x); ffma2(acc[2][1], dd2, v01.y);
        ffma2(acc[2][2], dd2, v23.x); ffma2(acc[2][3], dd2, v23.y);
    }

    // ---- barrier 2 wait, then epilogue (+C, store) --------------------------
    if (tid == 0) bar_wait(&g_bar2, tgt2);
    __syncthreads();

    #pragma unroll
    for (int ni = 0; ni < 3; ni++) {
        const int n = n0 + l + 32 * ni;
        if (n < N) {
            const int t = (step * n) % T;
            const ulonglong2 c0 = ldcg2(&g_C[(size_t)t * D + ob]);
            const ulonglong2 c1 = ldcg2(&g_C[(size_t)t * D + ob + 4]);
            fadd2(acc[ni][0], c0.x); fadd2(acc[ni][1], c0.y);
            fadd2(acc[ni][2], c1.x); fadd2(acc[ni][3], c1.y);
            ulonglong2 r0; r0.x = acc[ni][0]; r0.y = acc[ni][1];
            ulonglong2 r1; r1.x = acc[ni][2]; r1.y = acc[ni][3];
            *(ulonglong2*)&out[(size_t)n * D + ob]     = r0;
            *(ulonglong2*)&out[(size_t)n * D + ob + 4] = r1;
        }
    }
}

// ---------------------------------------------------------------------------
extern "C" void kernel_launch(void* const* d_in, const int* in_sizes, int n_in,
                              void* d_out, int out_size) {
    const float* embeds = (const float*)d_in[0];   // [N, 128]
    const float* dists  = (const float*)d_in[1];   // [64, N]
    const float* W      = (const float*)d_in[2];   // [128, 256]
    const float* b      = (const float*)d_in[3];   // [128]
    const int*   anchor = (const int*)  d_in[4];   // [64] int32
    float* out = (float*)d_out;

    const int N = in_sizes[0] / D;                 // 10000

    int g = AA, y = N;                             // g = gcd(64, N) = 16
    while (y) { int r = g % y; g = y; y = r; }
    const int T    = N / g;                        // 625
    const int step = AA / g;                       // 4

    const int nMain   = (N + TN - 1) / TN;         // 105
    const int nCtiles = (T + 7) / 8;               // 79
    const int grid    = nMain + NVB + 35;          // 148 (all resident; <= SM count)

    fused<<<grid, 512>>>(embeds, dists, W, b, anchor, out,
                         N, T, step, g, nMain, nCtiles);
}

// round 5
// speedup vs baseline: 1.3065x; 1.3065x over previous
#include <cuda_runtime.h>

#define D   128   // LATDIM
#define AA  64    // ANCHOR_SET_NUM
#define TN  96    // n per main tile -> 105 main blocks (single wave)
#define RW  5     // C-windows per k_pre tile (125 tiles for T=625)

// __device__ scratch (allocation-free rule)
__device__ float g_V[AA * D];
__device__ float g_C[10048 * D];

// ---------------------------------------------------------------------------
// packed f32x2 helpers (FFMA2 — PTX-only on sm_103a)
// ---------------------------------------------------------------------------
__device__ __forceinline__ unsigned long long pk2(float x, float y) {
    unsigned long long r;
    asm("mov.b64 %0, {%1, %2};" : "=l"(r) : "f"(x), "f"(y));
    return r;
}
__device__ __forceinline__ void unpk2(unsigned long long v, float& x, float& y) {
    asm("mov.b64 {%0, %1}, %2;" : "=f"(x), "=f"(y) : "l"(v));
}
__device__ __forceinline__ void ffma2(unsigned long long& a,
                                      unsigned long long b, unsigned long long c) {
    asm("fma.rn.f32x2 %0, %1, %2, %0;" : "+l"(a) : "l"(b), "l"(c));
}
__device__ __forceinline__ void fadd2(unsigned long long& a, unsigned long long b) {
    asm("add.rn.f32x2 %0, %0, %1;" : "+l"(a) : "l"(b));
}

// ---------------------------------------------------------------------------
// k_pre: one kernel computes BOTH
//   V[a][o] = (1/A) * sum_k embeds[anchor[a]][k] * W[o][k]          (8 blocks)
//   C[t][o] = (1/A) * sum_k E2[t][k] * W[o][D+k] + b[o]             (125 blocks)
//     with E2[t][k] = sum_{a<A} embeds[(g*t + a) mod N][k]
// computed straight from embeds (window sums inlined, no intermediate pass).
// 512 threads. grid = nC + AA/8 = 133 <= 148 (single wave).
// ---------------------------------------------------------------------------
__global__ __launch_bounds__(512)
void k_pre(const float* __restrict__ embeds,
           const float* __restrict__ W,
           const float* __restrict__ b,
           const int*   __restrict__ anchor,
           int N, int T, int g, int nC) {
    __shared__ __align__(16) float XT[D][8];   // [k][row], rows 8B-aligned pairs
    __shared__ float Wc[32][129];              // staged W chunk, transposed

    const int tid  = threadIdx.x;
    const bool isV = (blockIdx.x >= nC);
    const int  t0  = isV ? (blockIdx.x - nC) * 8 : blockIdx.x * RW;
    const int  R   = isV ? 8 : min(RW, T - t0);
    const int  woff = isV ? 0 : D;

    // ---- build XT[k][w] (w < 8; zero-fill beyond R) ----
    #pragma unroll
    for (int tsk = tid; tsk < 8 * D; tsk += 512) {
        const int w = tsk >> 7;
        const int k = tsk & 127;
        float val = 0.f;
        if (w < R) {
            if (isV) {
                val = __ldg(&embeds[(size_t)__ldg(&anchor[t0 + w]) * D + k]);
            } else {
                const int r0 = g * (t0 + w);
                float s0 = 0.f, s1 = 0.f, s2 = 0.f, s3 = 0.f;
                #pragma unroll 16
                for (int a = 0; a < AA; a += 4) {
                    int ra = r0 + a;
                    int r1i = ra + 1, r2i = ra + 2, r3i = ra + 3;
                    if (ra  >= N) ra  -= N;
                    if (r1i >= N) r1i -= N;
                    if (r2i >= N) r2i -= N;
                    if (r3i >= N) r3i -= N;
                    s0 += __ldg(&embeds[(size_t)ra  * D + k]);
                    s1 += __ldg(&embeds[(size_t)r1i * D + k]);
                    s2 += __ldg(&embeds[(size_t)r2i * D + k]);
                    s3 += __ldg(&embeds[(size_t)r3i * D + k]);
                }
                val = (s0 + s1) + (s2 + s3);
            }
        }
        XT[k][w] = val;
    }
    __syncthreads();

    // ---- gemm: thread = (o, row-pair tq). acc packs rows (2tq, 2tq+1) ----
    const int o  = tid & 127;
    const int tq = tid >> 7;
    unsigned long long acc = 0ull;

    #pragma unroll
    for (int kc = 0; kc < 4; kc++) {
        // stage Wc[k][o] for k in [32kc, 32kc+32), transposed, coalesced LDG
        #pragma unroll
        for (int it = 0; it < 2; it++) {
            const int idx  = tid + it * 512;          // 0..1023
            const int orow = idx >> 3;
            const int kq   = (idx & 7) * 4;
            const float4 wv = __ldg((const float4*)
                &W[(size_t)orow * (2 * D) + woff + kc * 32 + kq]);
            Wc[kq + 0][orow] = wv.x;
            Wc[kq + 1][orow] = wv.y;
            Wc[kq + 2][orow] = wv.z;
            Wc[kq + 3][orow] = wv.w;
        }
        __syncthreads();
        #pragma unroll
        for (int kk = 0; kk < 32; kk++) {
            const float wv = Wc[kk][o];                                // dense
            const unsigned long long x =
                *(const unsigned long long*)&XT[kc * 32 + kk][2 * tq]; // broadcast
            ffma2(acc, x, pk2(wv, wv));
        }
        __syncthreads();
    }

    // ---- epilogue ----
    float r0, r1;
    unpk2(acc, r0, r1);
    const float sc   = 1.0f / AA;
    const float bias = isV ? 0.f : __ldg(&b[o]);
    const int   row0 = 2 * tq;
    if (isV) {
        if (row0     < R) g_V[(t0 + row0)     * D + o] = r0 * sc;
        if (row0 + 1 < R) g_V[(t0 + row0 + 1) * D + o] = r1 * sc;
    } else {
        if (row0     < R) g_C[(size_t)(t0 + row0)     * D + o] = r0 * sc + bias;
        if (row0 + 1 < R) g_C[(size_t)(t0 + row0 + 1) * D + o] = r1 * sc + bias;
    }
}

// ---------------------------------------------------------------------------
// k_main: out[n][o] = sum_a dists[a][n] * V[a][o]  +  C[(step*n) mod T][o]
// 512 threads = 16 warps. warp -> o-chunk of 8; lane -> 3 n (stride 32).
// V via __ldg (L1-resident 32KB, warp-uniform); dists tile in smem.
// Explicit 1-deep prefetch of next-a operands to hide LDS/L1 latency.
// ---------------------------------------------------------------------------
__global__ __launch_bounds__(512)
void k_main(const float* __restrict__ dists,
            float* __restrict__ out,
            int N, int T, int step) {
    __shared__ float sd[AA][TN];   // 24 KB

    const int tid = threadIdx.x;
    const int n0  = blockIdx.x * TN;

    // stage dists tile (zero-padded tail): 3 float4 per thread
    #pragma unroll
    for (int i = tid; i < AA * TN / 4; i += 512) {
        const int a  = i / (TN / 4);
        const int j4 = (i % (TN / 4)) * 4;
        const int n  = n0 + j4;
        const float* src = dists + (size_t)a * N + n;
        float4 v;
        if (n + 3 < N) v = __ldg((const float4*)src);
        else {
            v.x = (n + 0 < N) ? src[0] : 0.f;
            v.y = (n + 1 < N) ? src[1] : 0.f;
            v.z = (n + 2 < N) ? src[2] : 0.f;
            v.w = (n + 3 < N) ? src[3] : 0.f;
        }
        ((float4*)sd)[i] = v;
    }
    __syncthreads();

    const int w  = tid >> 5;
    const int l  = tid & 31;
    const int ob = w * 8;

    unsigned long long acc[3][4];
    #pragma unroll
    for (int i = 0; i < 3; i++)
        #pragma unroll
        for (int j = 0; j < 4; j++) acc[i][j] = 0ull;

    // prefetch a = 0
    ulonglong2 v01 = __ldg((const ulonglong2*)&g_V[ob]);
    ulonglong2 v23 = __ldg((const ulonglong2*)&g_V[ob + 4]);
    float d0 = sd[0][l], d1 = sd[0][l + 32], d2 = sd[0][l + 64];

    #pragma unroll 8
    for (int a = 0; a < AA; a++) {
        // prefetch a+1 (wraps to 0 on last iter; value unused)
        const int an = (a + 1) & (AA - 1);
        const ulonglong2 nv01 = __ldg((const ulonglong2*)&g_V[an * D + ob]);
        const ulonglong2 nv23 = __ldg((const ulonglong2*)&g_V[an * D + ob + 4]);
        const float nd0 = sd[an][l];
        const float nd1 = sd[an][l + 32];
        const float nd2 = sd[an][l + 64];

        const unsigned long long dd0 = pk2(d0, d0);
        const unsigned long long dd1 = pk2(d1, d1);
        const unsigned long long dd2 = pk2(d2, d2);

        ffma2(acc[0][0], dd0, v01.x); ffma2(acc[0][1], dd0, v01.y);
        ffma2(acc[0][2], dd0, v23.x); ffma2(acc[0][3], dd0, v23.y);
        ffma2(acc[1][0], dd1, v01.x); ffma2(acc[1][1], dd1, v01.y);
        ffma2(acc[1][2], dd1, v23.x); ffma2(acc[1][3], dd1, v23.y);
        ffma2(acc[2][0], dd2, v01.x); ffma2(acc[2][1], dd2, v01.y);
        ffma2(acc[2][2], dd2, v23.x); ffma2(acc[2][3], dd2, v23.y);

        v01 = nv01; v23 = nv23; d0 = nd0; d1 = nd1; d2 = nd2;
    }

    // epilogue: add C[t(n)], store
    #pragma unroll
    for (int ni = 0; ni < 3; ni++) {
        const int n = n0 + l + 32 * ni;
        if (n < N) {
            const int t = (step * n) % T;
            const ulonglong2 c0 = __ldg((const ulonglong2*)&g_C[(size_t)t * D + ob]);
            const ulonglong2 c1 = __ldg((const ulonglong2*)&g_C[(size_t)t * D + ob + 4]);
            fadd2(acc[ni][0], c0.x); fadd2(acc[ni][1], c0.y);
            fadd2(acc[ni][2], c1.x); fadd2(acc[ni][3], c1.y);
            ulonglong2 r0; r0.x = acc[ni][0]; r0.y = acc[ni][1];
            ulonglong2 r1; r1.x = acc[ni][2]; r1.y = acc[ni][3];
            *(ulonglong2*)&out[(size_t)n * D + ob]     = r0;
            *(ulonglong2*)&out[(size_t)n * D + ob + 4] = r1;
        }
    }
}

// ---------------------------------------------------------------------------
extern "C" void kernel_launch(void* const* d_in, const int* in_sizes, int n_in,
                              void* d_out, int out_size) {
    const float* embeds = (const float*)d_in[0];   // [N, 128]
    const float* dists  = (const float*)d_in[1];   // [64, N]
    const float* W      = (const float*)d_in[2];   // [128, 256]
    const float* b      = (const float*)d_in[3];   // [128]
    const int*   anchor = (const int*)  d_in[4];   // [64] int32
    float* out = (float*)d_out;

    const int N = in_sizes[0] / D;                 // 10000

    int g = AA, y = N;                             // g = gcd(64, N) = 16
    while (y) { int r = g % y; g = y; y = r; }
    const int T    = N / g;                        // 625
    const int step = AA / g;                       // 4

    const int nC = (T + RW - 1) / RW;              // 125

    k_pre <<<nC + AA / 8, 512>>>(embeds, W, b, anchor, N, T, g, nC);
    k_main<<<(N + TN - 1) / TN, 512>>>(dists, out, N, T, step);
}

// round 6
// speedup vs baseline: 1.5165x; 1.1607x over previous
#include <cuda_runtime.h>

#define D   128   // LATDIM
#define AA  64    // ANCHOR_SET_NUM
#define TN  96    // n per main tile -> 105 blocks (single wave)
#define RW  5     // C-windows per k_pre tile (125 tiles for T=625)

// __device__ scratch (allocation-free rule)
__device__ float g_V[AA * D];
__device__ float g_C[10048 * D];

// ---------------------------------------------------------------------------
// packed f32x2 helpers (FFMA2 — PTX-only on sm_103a)
// ---------------------------------------------------------------------------
__device__ __forceinline__ unsigned long long pk2(float x, float y) {
    unsigned long long r;
    asm("mov.b64 %0, {%1, %2};" : "=l"(r) : "f"(x), "f"(y));
    return r;
}
__device__ __forceinline__ void unpk2(unsigned long long v, float& x, float& y) {
    asm("mov.b64 {%0, %1}, %2;" : "=f"(x), "=f"(y) : "l"(v));
}
__device__ __forceinline__ void ffma2(unsigned long long& a,
                                      unsigned long long b, unsigned long long c) {
    asm("fma.rn.f32x2 %0, %1, %2, %0;" : "+l"(a) : "l"(b), "l"(c));
}
__device__ __forceinline__ void fadd2(unsigned long long& a, unsigned long long b) {
    asm("add.rn.f32x2 %0, %0, %1;" : "+l"(a) : "l"(b));
}

// ---------------------------------------------------------------------------
// k_pre: computes BOTH (V tiles: 8 blocks; C tiles: 125 blocks)
//   V[a][o] = (1/A) * sum_k embeds[anchor[a]][k] * W[o][k]
//   C[t][o] = (1/A) * sum_k E2[t][k] * W[o][D+k] + b[o]
//     E2[t][k] = sum_{a<A} embeds[(g*t + a) mod N][k]  (window sums inlined)
// 512 threads. W chunks double-buffered so LDG staging overlaps FFMA2 compute.
// ---------------------------------------------------------------------------
__global__ __launch_bounds__(512)
void k_pre(const float* __restrict__ embeds,
           const float* __restrict__ W,
           const float* __restrict__ b,
           const int*   __restrict__ anchor,
           int N, int T, int g, int nC) {
    __shared__ __align__(16) float XT[D][8];   // [k][row]
    __shared__ float Wc[2][32][129];           // double-buffered W chunk

    const int tid  = threadIdx.x;
    const bool isV = (blockIdx.x >= nC);
    const int  t0  = isV ? (blockIdx.x - nC) * 8 : blockIdx.x * RW;
    const int  R   = isV ? 8 : min(RW, T - t0);
    const int  woff = isV ? 0 : D;

    // stage W chunk kc into buffer buf (transposed, coalesced float4 LDG)
    auto stageW = [&](int buf, int kc) {
        #pragma unroll
        for (int it = 0; it < 2; it++) {
            const int idx  = tid + it * 512;          // 0..1023
            const int orow = idx >> 3;
            const int kq   = (idx & 7) * 4;
            const float4 wv = __ldg((const float4*)
                &W[(size_t)orow * (2 * D) + woff + kc * 32 + kq]);
            Wc[buf][kq + 0][orow] = wv.x;
            Wc[buf][kq + 1][orow] = wv.y;
            Wc[buf][kq + 2][orow] = wv.z;
            Wc[buf][kq + 3][orow] = wv.w;
        }
    };

    stageW(0, 0);   // overlaps the XT build below

    // ---- build XT[k][w] (w < 8; zero-fill beyond R) ----
    #pragma unroll
    for (int tsk = tid; tsk < 8 * D; tsk += 512) {
        const int w = tsk >> 7;
        const int k = tsk & 127;
        float val = 0.f;
        if (w < R) {
            if (isV) {
                val = __ldg(&embeds[(size_t)__ldg(&anchor[t0 + w]) * D + k]);
            } else {
                const int r0 = g * (t0 + w);
                float s0 = 0.f, s1 = 0.f, s2 = 0.f, s3 = 0.f;
                #pragma unroll
                for (int a = 0; a < AA; a += 4) {
                    int ra = r0 + a;
                    int r1i = ra + 1, r2i = ra + 2, r3i = ra + 3;
                    if (ra  >= N) ra  -= N;
                    if (r1i >= N) r1i -= N;
                    if (r2i >= N) r2i -= N;
                    if (r3i >= N) r3i -= N;
                    s0 += __ldg(&embeds[(size_t)ra  * D + k]);
                    s1 += __ldg(&embeds[(size_t)r1i * D + k]);
                    s2 += __ldg(&embeds[(size_t)r2i * D + k]);
                    s3 += __ldg(&embeds[(size_t)r3i * D + k]);
                }
                val = (s0 + s1) + (s2 + s3);
            }
        }
        XT[k][w] = val;
    }
    __syncthreads();

    // ---- gemm: thread = (o, row-pair tq); acc packs rows (2tq, 2tq+1) ----
    const int o  = tid & 127;
    const int tq = tid >> 7;
    unsigned long long acc = 0ull;

    #pragma unroll
    for (int kc = 0; kc < 4; kc++) {
        if (kc < 3) stageW((kc + 1) & 1, kc + 1);   // prefetch next chunk
        #pragma unroll
        for (int kk = 0; kk < 32; kk++) {
            const float wv = Wc[kc & 1][kk][o];                        // dense
            const unsigned long long x =
                *(const unsigned long long*)&XT[kc * 32 + kk][2 * tq]; // broadcast
            ffma2(acc, x, pk2(wv, wv));
        }
        __syncthreads();
    }

    // ---- epilogue ----
    float r0, r1;
    unpk2(acc, r0, r1);
    const float sc   = 1.0f / AA;
    const float bias = isV ? 0.f : __ldg(&b[o]);
    const int   row0 = 2 * tq;
    if (isV) {
        if (row0     < R) g_V[(t0 + row0)     * D + o] = r0 * sc;
        if (row0 + 1 < R) g_V[(t0 + row0 + 1) * D + o] = r1 * sc;
    } else {
        if (row0     < R) g_C[(size_t)(t0 + row0)     * D + o] = r0 * sc + bias;
        if (row0 + 1 < R) g_C[(size_t)(t0 + row0 + 1) * D + o] = r1 * sc + bias;
    }
}

// ---------------------------------------------------------------------------
// k_main: out[n][o] = sum_a dists[a][n] * V[a][o]  +  C[(step*n) mod T][o]
// 512 threads = 16 warps; warp -> o-chunk of 8; lane -> n in {l, l+32, l+64}.
// BOTH operands in smem: V broadcast via uniform LDS.128 (no LDG in the inner
// loop — R5's uniform-LDG stream was LSU-queue-bound), dists dense LDS.32.
// fma-pipe bound: ~6.1K cyc.
// ---------------------------------------------------------------------------
__global__ __launch_bounds__(512)
void k_main(const float* __restrict__ dists,
            float* __restrict__ out,
            int N, int T, int step) {
    extern __shared__ __align__(16) float smem[];
    float (*sv)[D]  = (float(*)[D])smem;             // [64][128]  32 KB
    float (*sd)[TN] = (float(*)[TN])(smem + AA * D); // [64][96]   24 KB

    const int tid = threadIdx.x;
    const int n0  = blockIdx.x * TN;

    // stage V (2048 float4)
    #pragma unroll
    for (int i = tid; i < AA * D / 4; i += 512)
        ((float4*)sv)[i] = __ldg(((const float4*)g_V) + i);

    // stage dists tile (zero-padded tail)
    #pragma unroll
    for (int i = tid; i < AA * TN / 4; i += 512) {
        const int a  = i / (TN / 4);
        const int j4 = (i % (TN / 4)) * 4;
        const int n  = n0 + j4;
        const float* src = dists + (size_t)a * N + n;
        float4 v;
        if (n + 3 < N) v = __ldg((const float4*)src);
        else {
            v.x = (n + 0 < N) ? src[0] : 0.f;
            v.y = (n + 1 < N) ? src[1] : 0.f;
            v.z = (n + 2 < N) ? src[2] : 0.f;
            v.w = (n + 3 < N) ? src[3] : 0.f;
        }
        ((float4*)sd)[i] = v;
    }
    __syncthreads();

    const int w  = tid >> 5;
    const int l  = tid & 31;
    const int ob = w * 8;

    unsigned long long acc[3][4];
    #pragma unroll
    for (int i = 0; i < 3; i++)
        #pragma unroll
        for (int j = 0; j < 4; j++) acc[i][j] = 0ull;

    #pragma unroll
    for (int a = 0; a < AA; a++) {
        // V: warp-uniform smem loads (broadcast, conflict-free)
        const ulonglong2 v01 = *(const ulonglong2*)&sv[a][ob];
        const ulonglong2 v23 = *(const ulonglong2*)&sv[a][ob + 4];
        // d: dense conflict-free smem loads
        const float d0 = sd[a][l];
        const float d1 = sd[a][l + 32];
        const float d2 = sd[a][l + 64];
        const unsigned long long dd0 = pk2(d0, d0);
        const unsigned long long dd1 = pk2(d1, d1);
        const unsigned long long dd2 = pk2(d2, d2);

        ffma2(acc[0][0], dd0, v01.x); ffma2(acc[0][1], dd0, v01.y);
        ffma2(acc[0][2], dd0, v23.x); ffma2(acc[0][3], dd0, v23.y);
        ffma2(acc[1][0], dd1, v01.x); ffma2(acc[1][1], dd1, v01.y);
        ffma2(acc[1][2], dd1, v23.x); ffma2(acc[1][3], dd1, v23.y);
        ffma2(acc[2][0], dd2, v01.x); ffma2(acc[2][1], dd2, v01.y);
        ffma2(acc[2][2], dd2, v23.x); ffma2(acc[2][3], dd2, v23.y);
    }

    // epilogue: add C[t(n)], store
    #pragma unroll
    for (int ni = 0; ni < 3; ni++) {
        const int n = n0 + l + 32 * ni;
        if (n < N) {
            const int t = (step * n) % T;
            const ulonglong2 c0 = __ldg((const ulonglong2*)&g_C[(size_t)t * D + ob]);
            const ulonglong2 c1 = __ldg((const ulonglong2*)&g_C[(size_t)t * D + ob + 4]);
            fadd2(acc[ni][0], c0.x); fadd2(acc[ni][1], c0.y);
            fadd2(acc[ni][2], c1.x); fadd2(acc[ni][3], c1.y);
            ulonglong2 r0; r0.x = acc[ni][0]; r0.y = acc[ni][1];
            ulonglong2 r1; r1.x = acc[ni][2]; r1.y = acc[ni][3];
            *(ulonglong2*)&out[(size_t)n * D + ob]     = r0;
            *(ulonglong2*)&out[(size_t)n * D + ob + 4] = r1;
        }
    }
}

// ---------------------------------------------------------------------------
extern "C" void kernel_launch(void* const* d_in, const int* in_sizes, int n_in,
                              void* d_out, int out_size) {
    const float* embeds = (const float*)d_in[0];   // [N, 128]
    const float* dists  = (const float*)d_in[1];   // [64, N]
    const float* W      = (const float*)d_in[2];   // [128, 256]
    const float* b      = (const float*)d_in[3];   // [128]
    const int*   anchor = (const int*)  d_in[4];   // [64] int32
    float* out = (float*)d_out;

    const int N = in_sizes[0] / D;                 // 10000

    int g = AA, y = N;                             // g = gcd(64, N) = 16
    while (y) { int r = g % y; g = y; y = r; }
    const int T    = N / g;                        // 625
    const int step = AA / g;                       // 4

    const int nC = (T + RW - 1) / RW;              // 125
    const int smemMain = (AA * D + AA * TN) * (int)sizeof(float);  // 56 KB

    static bool attr_set = false;
    if (!attr_set) {
        cudaFuncSetAttribute(k_main, cudaFuncAttributeMaxDynamicSharedMemorySize,
                             smemMain);
        attr_set = true;
    }

    k_pre <<<nC + AA / 8, 512>>>(embeds, W, b, anchor, N, T, g, nC);
    k_main<<<(N + TN - 1) / TN, 512, smemMain>>>(dists, out, N, T, step);
}

// round 7
// speedup vs baseline: 1.7011x; 1.1217x over previous
#include <cuda_runtime.h>

#define D   128   // LATDIM
#define AA  64    // ANCHOR_SET_NUM
#define TN  96    // n per main tile -> 105 blocks (single wave)
#define RW  8     // rows per k_pre tile (79 C tiles + 8 V tiles = 87 blocks)

// __device__ scratch (allocation-free rule)
__device__ float g_V[AA * D];
__device__ float g_C[10048 * D];

// ---------------------------------------------------------------------------
// packed f32x2 helpers (FFMA2 — PTX-only on sm_103a)
// ---------------------------------------------------------------------------
__device__ __forceinline__ unsigned long long pk2(float x, float y) {
    unsigned long long r;
    asm("mov.b64 %0, {%1, %2};" : "=l"(r) : "f"(x), "f"(y));
    return r;
}
__device__ __forceinline__ void unpk2(unsigned long long v, float& x, float& y) {
    asm("mov.b64 {%0, %1}, %2;" : "=f"(x), "=f"(y) : "l"(v));
}
__device__ __forceinline__ void ffma2(unsigned long long& a,
                                      unsigned long long b, unsigned long long c) {
    asm("fma.rn.f32x2 %0, %1, %2, %0;" : "+l"(a) : "l"(b), "l"(c));
}
__device__ __forceinline__ void fadd2(unsigned long long& a, unsigned long long b) {
    asm("add.rn.f32x2 %0, %0, %1;" : "+l"(a) : "l"(b));
}

// ---------------------------------------------------------------------------
// k_pre: 1024 threads. Blocks [0,nC): C tiles of 8 windows. Blocks [nC,nC+8):
// V tiles of 8 anchors.
//   C[t][o] = (1/A) * sum_k E2[t][k] * W[o][D+k] + b[o]
//     E2[t][k] = sum of 64 consecutive embed rows (factored into 16-row chunks)
//   V[a][o] = (1/A) * sum_k embeds[anchor[a]][k] * W[o][k]
// All 4 W k-chunks staged up front; gemm split 4-way over k (h), smem-reduced.
// dyn smem: Wc 66048B + XT 4096B + sch/spart 12288B = 82432B
// ---------------------------------------------------------------------------
__global__ __launch_bounds__(1024)
void k_pre(const float* __restrict__ embeds,
           const float* __restrict__ W,
           const float* __restrict__ b,
           const int*   __restrict__ anchor,
           int N, int T, int nC) {
    extern __shared__ __align__(16) float sm[];
    float (*Wc)[32][129] = (float(*)[32][129])sm;           // [4][32][129]
    float (*XT)[8]       = (float(*)[8])(sm + 4 * 32 * 129);
    float* sch           = sm + 4 * 32 * 129 + D * 8;        // [11][2][128]
    unsigned long long* spart = (unsigned long long*)sch;    // overlay after gemm

    const int tid  = threadIdx.x;
    const int w    = tid >> 5;
    const int l    = tid & 31;
    const bool isV = (blockIdx.x >= nC);
    const int  t0  = isV ? (blockIdx.x - nC) * RW : blockIdx.x * RW;
    const int  R   = isV ? RW : min(RW, T - t0);
    const int  woff = isV ? 0 : D;

    // ---- stage all 4 W chunks (transposed, coalesced; 4 float4/thread) ----
    {
        const int orow = tid >> 3;
        const int kq   = (tid & 7) * 4;
        #pragma unroll
        for (int kc = 0; kc < 4; kc++) {
            const float4 wv = __ldg((const float4*)
                &W[(size_t)orow * (2 * D) + woff + kc * 32 + kq]);
            Wc[kc][kq + 0][orow] = wv.x;
            Wc[kc][kq + 1][orow] = wv.y;
            Wc[kc][kq + 2][orow] = wv.z;
            Wc[kc][kq + 3][orow] = wv.w;
        }
    }

    // ---- build XT[k][r] (source vectors, transposed) ----
    if (isV) {
        const int k = tid & 127, r = tid >> 7;
        XT[k][r] = __ldg(&embeds[(size_t)__ldg(&anchor[t0 + r]) * D + k]);
    } else {
        // 16-row chunk partial sums: warp (ch, half) sums 8 rows, lane -> 4 k
        const int ch = w >> 1, half = w & 1;
        if (ch < R + 3) {
            const int rbase = 16 * (t0 + ch) + 8 * half;
            float4 acc = {0.f, 0.f, 0.f, 0.f};
            #pragma unroll
            for (int i = 0; i < 8; i++) {
                int r = rbase + i; if (r >= N) r -= N;
                const float4 v = __ldg((const float4*)&embeds[(size_t)r * D + 4 * l]);
                acc.x += v.x; acc.y += v.y; acc.z += v.z; acc.w += v.w;
            }
            *(float4*)&sch[(ch * 2 + half) * 128 + 4 * l] = acc;
        }
        __syncthreads();
        // window r = chunks r..r+3 (both halves)
        const int k = tid & 127, r = tid >> 7;
        float val = 0.f;
        if (r < R) {
            #pragma unroll
            for (int c = 0; c < 4; c++)
                val += sch[((r + c) * 2 + 0) * 128 + k]
                     + sch[((r + c) * 2 + 1) * 128 + k];
        }
        XT[k][r] = val;
    }
    __syncthreads();

    // ---- gemm: thread (o, rq, h); h = k-chunk; rq = row-quad -------------
    const int o  = tid & 127;
    const int rq = (tid >> 7) & 1;
    const int h  = tid >> 8;
    unsigned long long a0 = 0ull, a1 = 0ull;   // rows (4rq,4rq+1),(4rq+2,4rq+3)

    #pragma unroll
    for (int kk = 0; kk < 32; kk++) {
        const float wv = Wc[h][kk][o];                          // dense LDS
        const ulonglong2 x = *(const ulonglong2*)&XT[h * 32 + kk][4 * rq]; // bcast
        const unsigned long long ww = pk2(wv, wv);
        ffma2(a0, x.x, ww);
        ffma2(a1, x.y, ww);
    }
    __syncthreads();   // gemm done; safe to overlay sch with spart

    if (h > 0) {
        ulonglong2 t; t.x = a0; t.y = a1;
        *(ulonglong2*)&spart[(((h - 1) * 256) + o * 2 + rq) * 2] = t;
    }
    __syncthreads();

    if (h == 0) {
        #pragma unroll
        for (int hh = 0; hh < 3; hh++) {
            const ulonglong2 t =
                *(const ulonglong2*)&spart[((hh * 256) + o * 2 + rq) * 2];
            fadd2(a0, t.x); fadd2(a1, t.y);
        }
        float r0, r1, r2, r3;
        unpk2(a0, r0, r1); unpk2(a1, r2, r3);
        float res[4] = {r0, r1, r2, r3};
        const float sc = 1.0f / AA;
        if (isV) {
            #pragma unroll
            for (int i = 0; i < 4; i++)
                g_V[(t0 + 4 * rq + i) * D + o] = res[i] * sc;
        } else {
            const float bias = __ldg(&b[o]);
            #pragma unroll
            for (int i = 0; i < 4; i++) {
                const int row = 4 * rq + i;
                if (row < R)
                    g_C[(size_t)(t0 + row) * D + o] = res[i] * sc + bias;
            }
        }
    }
}

// ---------------------------------------------------------------------------
// k_main: out[n][o] = sum_a dists[a][n] * V[a][o]  +  C[(step*n) mod T][o]
// 1024 threads = 32 warps (8/SMSP for latency hiding). Warp = (oc, ah):
// oc = o-chunk of 8, ah = a-half (32 anchors each). Lane -> 3 n (stride 32).
// ah=1 partials combined through smem (overlays sv/sd after mainloop).
// dyn smem: sv 32KB + sd 24KB = 57344B; spart overlay 48KB.
// ---------------------------------------------------------------------------
__global__ __launch_bounds__(1024)
void k_main(const float* __restrict__ dists,
            float* __restrict__ out,
            int N, int T, int step) {
    extern __shared__ __align__(16) float smem[];
    float (*sv)[D]  = (float(*)[D])smem;             // [64][128]  32 KB
    float (*sd)[TN] = (float(*)[TN])(smem + AA * D); // [64][96]   24 KB
    unsigned long long* spart = (unsigned long long*)smem; // [16][32][12] overlay

    const int tid = threadIdx.x;
    const int n0  = blockIdx.x * TN;

    // stage V (2048 float4, 2/thread)
    #pragma unroll
    for (int i = tid; i < AA * D / 4; i += 1024)
        ((float4*)sv)[i] = __ldg(((const float4*)g_V) + i);

    // stage dists tile (1536 float4, zero-padded tail)
    for (int i = tid; i < AA * TN / 4; i += 1024) {
        const int a  = i / (TN / 4);
        const int j4 = (i % (TN / 4)) * 4;
        const int n  = n0 + j4;
        const float* src = dists + (size_t)a * N + n;
        float4 v;
        if (n + 3 < N) v = __ldg((const float4*)src);
        else {
            v.x = (n + 0 < N) ? src[0] : 0.f;
            v.y = (n + 1 < N) ? src[1] : 0.f;
            v.z = (n + 2 < N) ? src[2] : 0.f;
            v.w = (n + 3 < N) ? src[3] : 0.f;
        }
        ((float4*)sd)[i] = v;
    }
    __syncthreads();

    const int w  = tid >> 5;
    const int l  = tid & 31;
    const int oc = w & 15;
    const int ah = w >> 4;           // a-half
    const int ob = oc * 8;
    const int a0 = ah * 32;

    unsigned long long acc[3][4];
    #pragma unroll
    for (int i = 0; i < 3; i++)
        #pragma unroll
        for (int j = 0; j < 4; j++) acc[i][j] = 0ull;

    #pragma unroll 8
    for (int a = a0; a < a0 + 32; a++) {
        const ulonglong2 v01 = *(const ulonglong2*)&sv[a][ob];      // broadcast
        const ulonglong2 v23 = *(const ulonglong2*)&sv[a][ob + 4];
        const float d0 = sd[a][l];                                   // dense
        const float d1 = sd[a][l + 32];
        const float d2 = sd[a][l + 64];
        const unsigned long long dd0 = pk2(d0, d0);
        const unsigned long long dd1 = pk2(d1, d1);
        const unsigned long long dd2 = pk2(d2, d2);

        ffma2(acc[0][0], dd0, v01.x); ffma2(acc[0][1], dd0, v01.y);
        ffma2(acc[0][2], dd0, v23.x); ffma2(acc[0][3], dd0, v23.y);
        ffma2(acc[1][0], dd1, v01.x); ffma2(acc[1][1], dd1, v01.y);
        ffma2(acc[1][2], dd1, v23.x); ffma2(acc[1][3], dd1, v23.y);
        ffma2(acc[2][0], dd2, v01.x); ffma2(acc[2][1], dd2, v01.y);
        ffma2(acc[2][2], dd2, v23.x); ffma2(acc[2][3], dd2, v23.y);
    }
    __syncthreads();   // all reads of sv/sd complete -> overlay with spart

    // a-half 1 publishes partials
    if (ah == 1) {
        unsigned long long* p = &spart[(oc * 32 + l) * 12];
        #pragma unroll
        for (int i = 0; i < 3; i++) {
            ulonglong2 t0v; t0v.x = acc[i][0]; t0v.y = acc[i][1];
            ulonglong2 t1v; t1v.x = acc[i][2]; t1v.y = acc[i][3];
            *(ulonglong2*)(p + 4 * i)     = t0v;
            *(ulonglong2*)(p + 4 * i + 2) = t1v;
        }
    }
    __syncthreads();

    if (ah == 0) {
        const unsigned long long* p = &spart[(oc * 32 + l) * 12];
        #pragma unroll
        for (int i = 0; i < 3; i++) {
            const ulonglong2 t0v = *(const ulonglong2*)(p + 4 * i);
            const ulonglong2 t1v = *(const ulonglong2*)(p + 4 * i + 2);
            fadd2(acc[i][0], t0v.x); fadd2(acc[i][1], t0v.y);
            fadd2(acc[i][2], t1v.x); fadd2(acc[i][3], t1v.y);
        }
        // epilogue: add C[t(n)], store
        #pragma unroll
        for (int ni = 0; ni < 3; ni++) {
            const int n = n0 + l + 32 * ni;
            if (n < N) {
                const int t = (step * n) % T;
                const ulonglong2 c0 = __ldg((const ulonglong2*)&g_C[(size_t)t * D + ob]);
                const ulonglong2 c1 = __ldg((const ulonglong2*)&g_C[(size_t)t * D + ob + 4]);
                fadd2(acc[ni][0], c0.x); fadd2(acc[ni][1], c0.y);
                fadd2(acc[ni][2], c1.x); fadd2(acc[ni][3], c1.y);
                ulonglong2 r0; r0.x = acc[ni][0]; r0.y = acc[ni][1];
                ulonglong2 r1; r1.x = acc[ni][2]; r1.y = acc[ni][3];
                *(ulonglong2*)&out[(size_t)n * D + ob]     = r0;
                *(ulonglong2*)&out[(size_t)n * D + ob + 4] = r1;
            }
        }
    }
}

// ---------------------------------------------------------------------------
extern "C" void kernel_launch(void* const* d_in, const int* in_sizes, int n_in,
                              void* d_out, int out_size) {
    const float* embeds = (const float*)d_in[0];   // [N, 128]
    const float* dists  = (const float*)d_in[1];   // [64, N]
    const float* W      = (const float*)d_in[2];   // [128, 256]
    const float* b      = (const float*)d_in[3];   // [128]
    const int*   anchor = (const int*)  d_in[4];   // [64] int32
    float* out = (float*)d_out;

    const int N = in_sizes[0] / D;                 // 10000

    int g = AA, y = N;                             // g = gcd(64, N) = 16
    while (y) { int r = g % y; g = y; y = r; }
    const int T    = N / g;                        // 625
    const int step = AA / g;                       // 4

    const int nC = (T + RW - 1) / RW;              // 79
    const int smemPre  = (4 * 32 * 129 + D * 8) * 4 + 12288;   // 82432 B
    const int smemMain = (AA * D + AA * TN) * (int)sizeof(float); // 57344 B

    cudaFuncSetAttribute(k_pre,  cudaFuncAttributeMaxDynamicSharedMemorySize, smemPre);
    cudaFuncSetAttribute(k_main, cudaFuncAttributeMaxDynamicSharedMemorySize, smemMain);

    k_pre <<<nC + AA / RW, 1024, smemPre>>>(embeds, W, b, anchor, N, T, nC);
    k_main<<<(N + TN - 1) / TN, 1024, smemMain>>>(dists, out, N, T, step);
}

// round 9
// speedup vs baseline: 2.0949x; 1.2315x over previous
#include <cuda_runtime.h>
#include <cstdint>

#define D   128   // LATDIM
#define AA  64    // ANCHOR_SET_NUM
#define MT  64    // n rows per main block -> grid 157
#define RW  8     // rows per k_pre tile
#define SDS 72    // sd stride (words); 72 % 32 == 8 -> conflict-free fragments
#define SVS 136   // sv stride (words); 136 % 32 == 8

// __device__ scratch (allocation-free rule)
__device__ float g_V[AA * D];       // [a][o]
__device__ float g_C[10048 * D];    // [t][o]

// ---------------------------------------------------------------------------
// packed f32x2 helpers (k_pre)
// ---------------------------------------------------------------------------
__device__ __forceinline__ unsigned long long pk2(float x, float y) {
    unsigned long long r;
    asm("mov.b64 %0, {%1, %2};" : "=l"(r) : "f"(x), "f"(y));
    return r;
}
__device__ __forceinline__ void unpk2(unsigned long long v, float& x, float& y) {
    asm("mov.b64 {%0, %1}, %2;" : "=f"(x), "=f"(y) : "l"(v));
}
__device__ __forceinline__ void ffma2(unsigned long long& a,
                                      unsigned long long b, unsigned long long c) {
    asm("fma.rn.f32x2 %0, %1, %2, %0;" : "+l"(a) : "l"(b), "l"(c));
}
__device__ __forceinline__ void fadd2(unsigned long long& a, unsigned long long b) {
    asm("add.rn.f32x2 %0, %0, %1;" : "+l"(a) : "l"(b));
}

// ---------------------------------------------------------------------------
// tf32 helpers (sm_80+ features -> fine on compute_103)
// ---------------------------------------------------------------------------
__device__ __forceinline__ uint32_t f2tf32(float f) {
    uint32_t r;
    asm("cvt.rna.tf32.f32 %0, %1;" : "=r"(r) : "f"(f));
    return r;
}
__device__ __forceinline__ void mma_tf32(float& c0, float& c1, float& c2, float& c3,
                                         uint32_t a0, uint32_t a1, uint32_t a2,
                                         uint32_t a3, uint32_t b0, uint32_t b1) {
    asm("mma.sync.aligned.m16n8k8.row.col.f32.tf32.tf32.f32 "
        "{%0,%1,%2,%3}, {%4,%5,%6,%7}, {%8,%9}, {%0,%1,%2,%3};"
        : "+f"(c0), "+f"(c1), "+f"(c2), "+f"(c3)
        : "r"(a0), "r"(a1), "r"(a2), "r"(a3), "r"(b0), "r"(b1));
}

// ---------------------------------------------------------------------------
// k_pre (structure proven in R7):
//   C[t][o] = (1/A) * sum_k E2[t][k] * W[o][D+k] + b[o]
//   V[a][o] = (1/A) * sum_k embeds[anchor[a]][k] * W[o][k]
// ---------------------------------------------------------------------------
__global__ __launch_bounds__(1024)
void k_pre(const float* __restrict__ embeds,
           const float* __restrict__ W,
           const float* __restrict__ b,
           const int*   __restrict__ anchor,
           int N, int T, int nC) {
    extern __shared__ __align__(16) float sm[];
    float (*Wc)[32][129] = (float(*)[32][129])sm;            // [4][32][129]
    float (*XT)[8]       = (float(*)[8])(sm + 4 * 32 * 129);
    float* sch           = sm + 4 * 32 * 129 + D * 8;        // [11][2][128]
    unsigned long long* spart = (unsigned long long*)sch;    // overlay after gemm

    const int tid  = threadIdx.x;
    const int w    = tid >> 5;
    const int l    = tid & 31;
    const bool isV = (blockIdx.x >= nC);
    const int  t0  = isV ? (blockIdx.x - nC) * RW : blockIdx.x * RW;
    const int  R   = isV ? RW : min(RW, T - t0);
    const int  woff = isV ? 0 : D;

    // stage all 4 W chunks (transposed, coalesced)
    {
        const int orow = tid >> 3;
        const int kq   = (tid & 7) * 4;
        #pragma unroll
        for (int kc = 0; kc < 4; kc++) {
            const float4 wv = __ldg((const float4*)
                &W[(size_t)orow * (2 * D) + woff + kc * 32 + kq]);
            Wc[kc][kq + 0][orow] = wv.x;
            Wc[kc][kq + 1][orow] = wv.y;
            Wc[kc][kq + 2][orow] = wv.z;
            Wc[kc][kq + 3][orow] = wv.w;
        }
    }

    // build XT[k][r]
    if (isV) {
        const int k = tid & 127, r = tid >> 7;
        XT[k][r] = __ldg(&embeds[(size_t)__ldg(&anchor[t0 + r]) * D + k]);
    } else {
        const int ch = w >> 1, half = w & 1;
        if (ch < R + 3) {
            const int rbase = 16 * (t0 + ch) + 8 * half;
            float4 acc = {0.f, 0.f, 0.f, 0.f};
            #pragma unroll
            for (int i = 0; i < 8; i++) {
                int r = rbase + i; if (r >= N) r -= N;
                const float4 v = __ldg((const float4*)&embeds[(size_t)r * D + 4 * l]);
                acc.x += v.x; acc.y += v.y; acc.z += v.z; acc.w += v.w;
            }
            *(float4*)&sch[(ch * 2 + half) * 128 + 4 * l] = acc;
        }
        __syncthreads();
        const int k = tid & 127, r = tid >> 7;
        float val = 0.f;
        if (r < R) {
            #pragma unroll
            for (int c = 0; c < 4; c++)
                val += sch[((r + c) * 2 + 0) * 128 + k]
                     + sch[((r + c) * 2 + 1) * 128 + k];
        }
        XT[k][r] = val;
    }
    __syncthreads();

    // gemm: thread (o, rq, h)
    const int o  = tid & 127;
    const int rq = (tid >> 7) & 1;
    const int h  = tid >> 8;
    unsigned long long a0 = 0ull, a1 = 0ull;

    #pragma unroll
    for (int kk = 0; kk < 32; kk++) {
        const float wv = Wc[h][kk][o];
        const ulonglong2 x = *(const ulonglong2*)&XT[h * 32 + kk][4 * rq];
        const unsigned long long ww = pk2(wv, wv);
        ffma2(a0, x.x, ww);
        ffma2(a1, x.y, ww);
    }
    __syncthreads();

    if (h > 0) {
        ulonglong2 t; t.x = a0; t.y = a1;
        *(ulonglong2*)&spart[(((h - 1) * 256) + o * 2 + rq) * 2] = t;
    }
    __syncthreads();

    if (h == 0) {
        #pragma unroll
        for (int hh = 0; hh < 3; hh++) {
            const ulonglong2 t =
                *(const ulonglong2*)&spart[((hh * 256) + o * 2 + rq) * 2];
            fadd2(a0, t.x); fadd2(a1, t.y);
        }
        float r0, r1, r2, r3;
        unpk2(a0, r0, r1); unpk2(a1, r2, r3);
        float res[4] = {r0, r1, r2, r3};
        const float sc = 1.0f / AA;
        if (isV) {
            #pragma unroll
            for (int i = 0; i < 4; i++)
                g_V[(t0 + 4 * rq + i) * D + o] = res[i] * sc;
        } else {
            const float bias = __ldg(&b[o]);
            #pragma unroll
            for (int i = 0; i < 4; i++) {
                const int row = 4 * rq + i;
                if (row < R)
                    g_C[(size_t)(t0 + row) * D + o] = res[i] * sc + bias;
            }
        }
    }
}

// ---------------------------------------------------------------------------
// k_main_mma: out[n][o] = sum_a Dt[n][a]*V[a][o] + C[t(n)][o] via tf32 mma.sync
// 256 threads = 8 warps: warp = (mw 0..3 -> 16 n-rows, nh 0..1 -> 64 o-cols).
// Operands staged as tf32 bits in smem; strides 72/136 (≡ 8 mod 32) make all
// fragment LDS conflict-free (banks 8*tig + g).
// ---------------------------------------------------------------------------
__global__ __launch_bounds__(256)
void k_main_mma(const float* __restrict__ dists,
                float* __restrict__ out,
                int N, int T, int step) {
    extern __shared__ __align__(16) uint32_t smem[];
    uint32_t* sd = smem;             // [64][SDS]  Dt tile: sd[a][n]
    uint32_t* sv = smem + AA * SDS;  // [64][SVS]  V:       sv[a][o]

    const int tid = threadIdx.x;
    const int n0  = blockIdx.x * MT;

    // stage sd (dists tile, converted to tf32; zero-pad tail)
    #pragma unroll
    for (int i = tid; i < AA * (MT / 4); i += 256) {
        const int a  = i / (MT / 4);
        const int j4 = (i % (MT / 4)) * 4;
        const int n  = n0 + j4;
        const float* src = dists + (size_t)a * N + n;
        float4 v;
        if (n + 3 < N) v = __ldg((const float4*)src);
        else {
            v.x = (n + 0 < N) ? src[0] : 0.f;
            v.y = (n + 1 < N) ? src[1] : 0.f;
            v.z = (n + 2 < N) ? src[2] : 0.f;
            v.w = (n + 3 < N) ? src[3] : 0.f;
        }
        uint4 t;
        t.x = f2tf32(v.x); t.y = f2tf32(v.y);
        t.z = f2tf32(v.z); t.w = f2tf32(v.w);
        *(uint4*)&sd[a * SDS + j4] = t;
    }
    // stage sv (V, converted to tf32)
    #pragma unroll
    for (int i = tid; i < AA * (D / 4); i += 256) {
        const int a  = i >> 5;
        const int o4 = (i & 31) * 4;
        const float4 v = __ldg((const float4*)&g_V[a * D + o4]);
        uint4 t;
        t.x = f2tf32(v.x); t.y = f2tf32(v.y);
        t.z = f2tf32(v.z); t.w = f2tf32(v.w);
        *(uint4*)&sv[a * SVS + o4] = t;
    }
    __syncthreads();

    const int w   = tid >> 5;
    const int l   = tid & 31;
    const int tig = l & 3;          // threadID in group
    const int g   = l >> 2;         // group id
    const int mw  = w & 3;          // m16 tile
    const int nh  = w >> 2;         // o-half
    const int rowbase = 16 * mw;
    const int obase   = 64 * nh;

    float c[8][4];
    #pragma unroll
    for (int j = 0; j < 8; j++)
        #pragma unroll
        for (int q = 0; q < 4; q++) c[j][q] = 0.f;

    #pragma unroll
    for (int ks = 0; ks < 8; ks++) {
        const int k0 = 8 * ks + tig;
        // A fragment (row-major m16k8): a0(r,k) a1(r+8,k) a2(r,k+4) a3(r+8,k+4)
        const uint32_t a0 = sd[k0 * SDS + rowbase + g];
        const uint32_t a1 = sd[k0 * SDS + rowbase + g + 8];
        const uint32_t a2 = sd[(k0 + 4) * SDS + rowbase + g];
        const uint32_t a3 = sd[(k0 + 4) * SDS + rowbase + g + 8];
        #pragma unroll
        for (int j = 0; j < 8; j++) {
            // B fragment (col, k8n8): b0(k=tig, n=g), b1(k=tig+4, n=g)
            const uint32_t b0 = sv[k0 * SVS + obase + 8 * j + g];
            const uint32_t b1 = sv[(k0 + 4) * SVS + obase + 8 * j + g];
            mma_tf32(c[j][0], c[j][1], c[j][2], c[j][3], a0, a1, a2, a3, b0, b1);
        }
    }

    // epilogue: c0,c1 -> (row=g, col=2tig,2tig+1); c2,c3 -> row=g+8
    const int n_lo = n0 + rowbase + g;
    const int n_hi = n_lo + 8;
    const int t_lo = (n_lo < N) ? (step * n_lo) % T : 0;
    const int t_hi = (n_hi < N) ? (step * n_hi) % T : 0;

    #pragma unroll
    for (int j = 0; j < 8; j++) {
        const int col = obase + 8 * j + 2 * tig;
        if (n_lo < N) {
            const float2 cc = __ldg((const float2*)&g_C[(size_t)t_lo * D + col]);
            float2 r; r.x = c[j][0] + cc.x; r.y = c[j][1] + cc.y;
            *(float2*)&out[(size_t)n_lo * D + col] = r;
        }
        if (n_hi < N) {
            const float2 cc = __ldg((const float2*)&g_C[(size_t)t_hi * D + col]);
            float2 r; r.x = c[j][2] + cc.x; r.y = c[j][3] + cc.y;
            *(float2*)&out[(size_t)n_hi * D + col] = r;
        }
    }
}

// ---------------------------------------------------------------------------
extern "C" void kernel_launch(void* const* d_in, const int* in_sizes, int n_in,
                              void* d_out, int out_size) {
    const float* embeds = (const float*)d_in[0];   // [N, 128]
    const float* dists  = (const float*)d_in[1];   // [64, N]
    const float* W      = (const float*)d_in[2];   // [128, 256]
    const float* b      = (const float*)d_in[3];   // [128]
    const int*   anchor = (const int*)  d_in[4];   // [64] int32
    float* out = (float*)d_out;

    const int N = in_sizes[0] / D;                 // 10000

    int g = AA, y = N;                             // gcd(64, N) = 16
    while (y) { int r = g % y; g = y; y = r; }
    const int T    = N / g;                        // 625
    const int step = AA / g;                       // 4

    const int nC = (T + RW - 1) / RW;              // 79
    const int smemPre = (4 * 32 * 129 + D * 8) * 4 + 12288;        // 82432 B
    const int smemMMA = (AA * SDS + AA * SVS) * (int)sizeof(float); // 53248 B

    cudaFuncSetAttribute(k_pre, cudaFuncAttributeMaxDynamicSharedMemorySize, smemPre);
    cudaFuncSetAttribute(k_main_mma, cudaFuncAttributeMaxDynamicSharedMemorySize, smemMMA);

    k_pre    <<<nC + AA / RW, 1024, smemPre>>>(embeds, W, b, anchor, N, T, nC);
    k_main_mma<<<(N + MT - 1) / MT, 256, smemMMA>>>(dists, out, N, T, step);
}